// round 8
// baseline (speedup 1.0000x reference)
#include <cuda_runtime.h>
#include <cuda_fp16.h>

// BSplineACTF: per-channel cubic B-spline activation, uniform knots.
// x:[16,256,256,32] f32, grid:[12] f32, W:[32,8] f32 -> out f32.
//
// R8 consolidation (kernel is memory-bound at ~6.6 TB/s effective):
//  - R6 hot loop: magic-add floor (no XU ops), 13-slot zero-padded table,
//    fp16-packed collapsed cubic, one LDS.64 + 3 FMA per element.
//  - 13-uint2 row stride is conflict-free across the warp's channel/slot mix.
//  - Grid 1184 = 8 blocks/SM = ONE full-occupancy wave (no wave transition,
//    half the table builds vs 2368).

#define NTHREADS 256
#define NBLOCKS  1184   // 148 SMs x 8 blocks x 8 warps = one full wave

#define MAGIC_F   6291456.0f        // 1.5 * 2^22, ULP = 0.5 in its binade
#define MAGIC_I   0x4AC00000        // __float_as_int(6291456.0f)

__global__ __launch_bounds__(NTHREADS) void bspline_actf_kernel(
    const float* __restrict__ x,
    const float* __restrict__ grid,
    const float* __restrict__ W,
    float* __restrict__ out,
    int n)
{
    // [channel][slot] packed cubic coeffs: lo=(c0,c1), hi=(c2,c3) as half2.
    // slot s corresponds to interval j = s-1; s=0 and s=12 are zero rows.
    __shared__ uint2 sc[32 * 13];

    const float g0    = grid[0];
    const float g11   = grid[11];
    const float h     = (g11 - g0) * (1.0f / 11.0f);
    const float inv_h = 1.0f / h;
    // us = (x - g0)*inv_h + 1 (row shift) - 0.25 (floor-trick offset)
    const float bias  = -g0 * inv_h + 0.75f;

    // ---- one-time per-block coefficient build (416 records) ----
    for (int idx = threadIdx.x; idx < 32 * 13; idx += NTHREADS) {
        int c = idx / 13;
        int s = idx - c * 13;
        int j = s - 1;
        uint2 rec = make_uint2(0u, 0u);
        if (j >= 0 && j <= 10) {
            const float* Wc = W + c * 8;
            float w0 = (j     >= 0 && j     < 8) ? __ldg(Wc + j)     : 0.0f;
            float w1 = (j - 1 >= 0 && j - 1 < 8) ? __ldg(Wc + j - 1) : 0.0f;
            float w2 = (j - 2 >= 0 && j - 2 < 8) ? __ldg(Wc + j - 2) : 0.0f;
            float w3 = (j - 3 >= 0 && j - 3 < 8) ? __ldg(Wc + j - 3) : 0.0f;
            float c0 = (w1 + 4.0f * w2 + w3) * (1.0f / 6.0f);
            float c1 = (w1 - w3) * 0.5f;
            float c2 = (w1 - 2.0f * w2 + w3) * 0.5f;
            float c3 = (w0 - 3.0f * w1 + 3.0f * w2 - w3) * (1.0f / 6.0f);
            __half2 lo = __floats2half2_rn(c0, c1);
            __half2 hi = __floats2half2_rn(c2, c3);
            rec.x = *reinterpret_cast<unsigned int*>(&lo);
            rec.y = *reinterpret_cast<unsigned int*>(&hi);
        }
        sc[idx] = rec;
    }
    __syncthreads();

    const int gtid   = blockIdx.x * NTHREADS + threadIdx.x;
    const int stride = gridDim.x * NTHREADS;   // in float4 vectors; % 8 == 0
    const int n4     = n >> 2;

    // channel quartet of this thread's vectors is loop-invariant
    const int c0i = (gtid & 7) * 4;
    const uint2* __restrict__ row0 = sc + (c0i + 0) * 13;
    const uint2* __restrict__ row1 = sc + (c0i + 1) * 13;
    const uint2* __restrict__ row2 = sc + (c0i + 2) * 13;
    const uint2* __restrict__ row3 = sc + (c0i + 3) * 13;

    const float4* __restrict__ x4 = (const float4*)x;
    float4* __restrict__ o4       = (float4*)out;

    auto evalspline = [&](float xv, const uint2* __restrict__ rowp) -> float {
        // us = floor-target - 0.25; clamp keeps slot in [0, 12]
        float us = fmaf(xv, inv_h, bias);
        us = fminf(fmaxf(us, -0.25f), 12.25f);
        float f  = us + MAGIC_F;                 // round-to-nearest-0.5 of us
        int idx2 = __float_as_int(f) - MAGIC_I;  // = 2*r', r' = rounded us
        float rp = f - MAGIC_F;                  // r' exactly
        float d  = us - rp;                      // in [-0.25, 0.25)
        int   s  = idx2 >> 1;                    // floor(us + 0.25) = slot
        float t  = d + ((idx2 & 1) ? 0.75f : 0.25f);
        uint2 rec = rowp[s];                     // LDS.64
        __half2 lo = *reinterpret_cast<__half2*>(&rec.x);
        __half2 hi = *reinterpret_cast<__half2*>(&rec.y);
        float2 f01 = __half22float2(lo);
        float2 f23 = __half22float2(hi);
        return fmaf(fmaf(fmaf(f23.y, t, f23.x), t, f01.y), t, f01.x);
    };

    auto eval_vec = [&](float4 xv) -> float4 {
        float4 ov;
        ov.x = evalspline(xv.x, row0);
        ov.y = evalspline(xv.y, row1);
        ov.z = evalspline(xv.z, row2);
        ov.w = evalspline(xv.w, row3);
        return ov;
    };

    // 2-way unrolled grid-stride loop
    int v = gtid;
    for (; v + stride < n4; v += 2 * stride) {
        float4 xa = x4[v];
        float4 xb = x4[v + stride];
        float4 oa = eval_vec(xa);
        float4 ob = eval_vec(xb);
        o4[v]          = oa;
        o4[v + stride] = ob;
    }
    if (v < n4) {
        o4[v] = eval_vec(x4[v]);
    }

    // scalar tail (n % 4) — not hit for this shape, kept for safety
    for (int e = (n4 << 2) + gtid; e < n; e += stride) {
        int c = e & 31;
        out[e] = evalspline(x[e], sc + c * 13);
    }
}

extern "C" void kernel_launch(void* const* d_in, const int* in_sizes, int n_in,
                              void* d_out, int out_size)
{
    const float* x    = (const float*)d_in[0];
    const float* grid = (const float*)d_in[1];
    const float* W    = (const float*)d_in[2];
    float* out        = (float*)d_out;
    int n = in_sizes[0];

    int n4 = n >> 2;
    int blocks = NBLOCKS;
    int maxBlocks = (n4 + NTHREADS - 1) / NTHREADS;
    if (maxBlocks < 1) maxBlocks = 1;
    if (blocks > maxBlocks) blocks = maxBlocks;

    bspline_actf_kernel<<<blocks, NTHREADS>>>(x, grid, W, out, n);
}

// round 9
// speedup vs baseline: 1.1297x; 1.1297x over previous
#include <cuda_runtime.h>
#include <cuda_fp16.h>

// BSplineACTF: per-channel cubic B-spline activation, uniform knots.
// x:[16,256,256,32] f32, grid:[12] f32, W:[32,8] f32 -> out f32.
//
// R9 = best measured WALL config (R4: 4-way unroll, front-batched __ldcs,
// __stcs stores, 2368 blocks) + best hot loop (R6: magic-add floor, no
// converter ops, 13-slot zero-padded fp16 table, conflict-free 13-uint2
// stride, one LDS.64 + 3 FMA per element).

#define NTHREADS 256
#define NBLOCKS  2368

#define MAGIC_F   6291456.0f        // 1.5 * 2^22, ULP = 0.5 in its binade
#define MAGIC_I   0x4AC00000        // __float_as_int(6291456.0f)

__global__ __launch_bounds__(NTHREADS) void bspline_actf_kernel(
    const float* __restrict__ x,
    const float* __restrict__ grid,
    const float* __restrict__ W,
    float* __restrict__ out,
    int n)
{
    // [channel][slot] packed cubic coeffs: lo=(c0,c1), hi=(c2,c3) as half2.
    // slot s corresponds to interval j = s-1; s=0 and s=12 are zero rows.
    __shared__ uint2 sc[32 * 13];

    const float g0    = grid[0];
    const float g11   = grid[11];
    const float h     = (g11 - g0) * (1.0f / 11.0f);
    const float inv_h = 1.0f / h;
    // us = (x - g0)*inv_h + 1 (row shift) - 0.25 (floor-trick offset)
    const float bias  = -g0 * inv_h + 0.75f;

    // ---- one-time per-block coefficient build (416 records) ----
    for (int idx = threadIdx.x; idx < 32 * 13; idx += NTHREADS) {
        int c = idx / 13;
        int s = idx - c * 13;
        int j = s - 1;
        uint2 rec = make_uint2(0u, 0u);
        if (j >= 0 && j <= 10) {
            const float* Wc = W + c * 8;
            float w0 = (j     >= 0 && j     < 8) ? __ldg(Wc + j)     : 0.0f;
            float w1 = (j - 1 >= 0 && j - 1 < 8) ? __ldg(Wc + j - 1) : 0.0f;
            float w2 = (j - 2 >= 0 && j - 2 < 8) ? __ldg(Wc + j - 2) : 0.0f;
            float w3 = (j - 3 >= 0 && j - 3 < 8) ? __ldg(Wc + j - 3) : 0.0f;
            float c0 = (w1 + 4.0f * w2 + w3) * (1.0f / 6.0f);
            float c1 = (w1 - w3) * 0.5f;
            float c2 = (w1 - 2.0f * w2 + w3) * 0.5f;
            float c3 = (w0 - 3.0f * w1 + 3.0f * w2 - w3) * (1.0f / 6.0f);
            __half2 lo = __floats2half2_rn(c0, c1);
            __half2 hi = __floats2half2_rn(c2, c3);
            rec.x = *reinterpret_cast<unsigned int*>(&lo);
            rec.y = *reinterpret_cast<unsigned int*>(&hi);
        }
        sc[idx] = rec;
    }
    __syncthreads();

    const int gtid   = blockIdx.x * NTHREADS + threadIdx.x;
    const int stride = gridDim.x * NTHREADS;   // in float4 vectors; % 8 == 0
    const int n4     = n >> 2;

    // channel quartet of this thread's vectors is loop-invariant
    const int c0i = (gtid & 7) * 4;
    const uint2* __restrict__ row0 = sc + (c0i + 0) * 13;
    const uint2* __restrict__ row1 = sc + (c0i + 1) * 13;
    const uint2* __restrict__ row2 = sc + (c0i + 2) * 13;
    const uint2* __restrict__ row3 = sc + (c0i + 3) * 13;

    const float4* __restrict__ x4 = (const float4*)x;
    float4* __restrict__ o4       = (float4*)out;

    auto evalspline = [&](float xv, const uint2* __restrict__ rowp) -> float {
        // us = floor-target - 0.25; clamp keeps slot in [0, 12]
        float us = fmaf(xv, inv_h, bias);
        us = fminf(fmaxf(us, -0.25f), 12.25f);
        float f  = us + MAGIC_F;                 // round-to-nearest-0.5 of us
        int idx2 = __float_as_int(f) - MAGIC_I;  // = 2*r', r' = rounded us
        float rp = f - MAGIC_F;                  // r' exactly
        float d  = us - rp;                      // in [-0.25, 0.25)
        int   s  = idx2 >> 1;                    // floor(us + 0.25) = slot
        float t  = d + ((idx2 & 1) ? 0.75f : 0.25f);
        uint2 rec = rowp[s];                     // LDS.64
        __half2 lo = *reinterpret_cast<__half2*>(&rec.x);
        __half2 hi = *reinterpret_cast<__half2*>(&rec.y);
        float2 f01 = __half22float2(lo);
        float2 f23 = __half22float2(hi);
        return fmaf(fmaf(fmaf(f23.y, t, f23.x), t, f01.y), t, f01.x);
    };

    auto eval_vec = [&](float4 xv) -> float4 {
        float4 ov;
        ov.x = evalspline(xv.x, row0);
        ov.y = evalspline(xv.y, row1);
        ov.z = evalspline(xv.z, row2);
        ov.w = evalspline(xv.w, row3);
        return ov;
    };

    // 4-way unrolled grid-stride loop: 4 independent LDG.128 front-batched.
    int v = gtid;
    for (; v + 3 * stride < n4; v += 4 * stride) {
        float4 xa = __ldcs(&x4[v]);
        float4 xb = __ldcs(&x4[v + stride]);
        float4 xc = __ldcs(&x4[v + 2 * stride]);
        float4 xd = __ldcs(&x4[v + 3 * stride]);
        float4 oa = eval_vec(xa);
        float4 ob = eval_vec(xb);
        float4 oc = eval_vec(xc);
        float4 od = eval_vec(xd);
        __stcs(&o4[v],              oa);
        __stcs(&o4[v + stride],     ob);
        __stcs(&o4[v + 2 * stride], oc);
        __stcs(&o4[v + 3 * stride], od);
    }
    for (; v < n4; v += stride) {
        float4 xv = __ldcs(&x4[v]);
        float4 ov = eval_vec(xv);
        __stcs(&o4[v], ov);
    }

    // scalar tail (n % 4) — not hit for this shape, kept for safety
    for (int e = (n4 << 2) + gtid; e < n; e += stride) {
        int c = e & 31;
        out[e] = evalspline(x[e], sc + c * 13);
    }
}

extern "C" void kernel_launch(void* const* d_in, const int* in_sizes, int n_in,
                              void* d_out, int out_size)
{
    const float* x    = (const float*)d_in[0];
    const float* grid = (const float*)d_in[1];
    const float* W    = (const float*)d_in[2];
    float* out        = (float*)d_out;
    int n = in_sizes[0];

    int n4 = n >> 2;
    int blocks = NBLOCKS;
    int maxBlocks = (n4 + NTHREADS - 1) / NTHREADS;
    if (maxBlocks < 1) maxBlocks = 1;
    if (blocks > maxBlocks) blocks = maxBlocks;

    bspline_actf_kernel<<<blocks, NTHREADS>>>(x, grid, W, out, n);
}